// round 1
// baseline (speedup 1.0000x reference)
#include <cuda_runtime.h>
#include <math.h>

#define L_SEQ   4097
#define BLTOT   8194            // B * L_SEQ
#define DMODEL  256
#define DINNER  512
#define NCH     64              // scan chunks
#define CSZ     65              // chunk size (64*65 = 4160 >= 4097)

// ---------------- scratch (static device globals; no runtime alloc) --------
__device__ float g_e   [2048 * 1024];
__device__ float g_xx  [BLTOT * DMODEL];
__device__ float g_xz  [BLTOT * 1024];
__device__ float g_xi  [BLTOT * DINNER];
__device__ float g_dbc [BLTOT * 48];
__device__ float g_delta[BLTOT * DINNER];
__device__ float g_y   [BLTOT * DINNER];
__device__ float g_P   [2 * NCH * DINNER * 16];
__device__ float g_Q   [2 * NCH * DINNER * 16];
__device__ float g_H   [2 * NCH * DINNER * 16];
__device__ float g_part [64 * 256];
__device__ float g_part2[64 * 256];
__device__ float g_mean[256];
__device__ float g_inv [256];

// ---------------- generic fp32 GEMM:  C[M,N] = A[M,K] * W[N,K]^T -----------
// BM=BN=128, BK=16, 256 threads, 8x8 microtile per thread.
__global__ void __launch_bounds__(256)
gemm_nt_kernel(const float* __restrict__ A, const float* __restrict__ W,
               float* __restrict__ C, int M, int N, int K)
{
    __shared__ __align__(16) float As[16][128];
    __shared__ __align__(16) float Ws[16][128];
    const int tid = threadIdx.x;
    const int m0 = blockIdx.y * 128;
    const int n0 = blockIdx.x * 128;
    const int tr = tid >> 4;
    const int tc = tid & 15;
    const int rowBase = tr * 8;
    const int colBase = tc * 8;

    float acc[8][8];
#pragma unroll
    for (int i = 0; i < 8; i++)
#pragma unroll
        for (int j = 0; j < 8; j++) acc[i][j] = 0.f;

    for (int k0 = 0; k0 < K; k0 += 16) {
#pragma unroll
        for (int f = tid; f < 512; f += 256) {
            int r  = f >> 2;
            int c4 = (f & 3) << 2;
            int gm = m0 + r;
            float4 v = make_float4(0.f, 0.f, 0.f, 0.f);
            if (gm < M)
                v = *reinterpret_cast<const float4*>(A + (size_t)gm * K + k0 + c4);
            As[c4 + 0][r] = v.x; As[c4 + 1][r] = v.y;
            As[c4 + 2][r] = v.z; As[c4 + 3][r] = v.w;
        }
#pragma unroll
        for (int f = tid; f < 512; f += 256) {
            int r  = f >> 2;
            int c4 = (f & 3) << 2;
            int gn = n0 + r;
            float4 v = make_float4(0.f, 0.f, 0.f, 0.f);
            if (gn < N)
                v = *reinterpret_cast<const float4*>(W + (size_t)gn * K + k0 + c4);
            Ws[c4 + 0][r] = v.x; Ws[c4 + 1][r] = v.y;
            Ws[c4 + 2][r] = v.z; Ws[c4 + 3][r] = v.w;
        }
        __syncthreads();
#pragma unroll
        for (int kk = 0; kk < 16; kk++) {
            const float4* Ar = reinterpret_cast<const float4*>(&As[kk][rowBase]);
            const float4* Br = reinterpret_cast<const float4*>(&Ws[kk][colBase]);
            float4 a0 = Ar[0], a1 = Ar[1];
            float4 b0 = Br[0], b1 = Br[1];
            float a[8] = {a0.x, a0.y, a0.z, a0.w, a1.x, a1.y, a1.z, a1.w};
            float b[8] = {b0.x, b0.y, b0.z, b0.w, b1.x, b1.y, b1.z, b1.w};
#pragma unroll
            for (int i = 0; i < 8; i++)
#pragma unroll
                for (int j = 0; j < 8; j++)
                    acc[i][j] = fmaf(a[i], b[j], acc[i][j]);
        }
        __syncthreads();
    }
#pragma unroll
    for (int i = 0; i < 8; i++) {
        int gm = m0 + rowBase + i;
        if (gm >= M) continue;
#pragma unroll
        for (int j = 0; j < 8; j++) {
            int gn = n0 + colBase + j;
            if (gn < N) C[(size_t)gm * N + gn] = acc[i][j];
        }
    }
}

// ---------------- pixel-shuffle + LayerNorm + skip -------------------------
// one block per (row in 0..2047, cpq in 0..3); 256 threads = channel m
__global__ void shuffle_ln_kernel(const float* __restrict__ skip,
                                  const float* __restrict__ ln_g,
                                  const float* __restrict__ ln_b)
{
    int blk = blockIdx.x;
    int row = blk >> 2;          // b*1024 + t*256 + n
    int cpq = blk & 3;
    int tid = threadIdx.x;
    int b = row >> 10;
    int t = (row >> 8) & 3;
    int n = row & 255;

    float v = g_e[(size_t)row * 1024 + cpq * 256 + tid];

    float s = v, s2 = v * v;
#pragma unroll
    for (int o = 16; o; o >>= 1) {
        s  += __shfl_xor_sync(0xffffffffu, s,  o);
        s2 += __shfl_xor_sync(0xffffffffu, s2, o);
    }
    __shared__ float ss[8], ss2[8];
    __shared__ float smean, svar;
    int lane = tid & 31, wid = tid >> 5;
    if (lane == 0) { ss[wid] = s; ss2[wid] = s2; }
    __syncthreads();
    if (tid == 0) {
        float S = 0.f, S2 = 0.f;
#pragma unroll
        for (int i = 0; i < 8; i++) { S += ss[i]; S2 += ss2[i]; }
        float mu = S * (1.f / 256.f);
        smean = mu;
        svar  = S2 * (1.f / 256.f) - mu * mu;
    }
    __syncthreads();
    float y = (v - smean) * rsqrtf(svar + 1e-5f) * ln_g[tid] + ln_b[tid];

    int h = n >> 4, w = n & 15, p = cpq >> 1, q = cpq & 1;
    int j = h * 64 + p * 32 + w * 2 + q;
    size_t pos = ((size_t)b * L_SEQ + 1 + t * 1024 + j) * 256 + tid;
    g_xx[pos] = y + skip[pos];
}

// ---------------- cls token projection + skip ------------------------------
__global__ void cls_kernel(const float* __restrict__ x,
                           const float* __restrict__ cls_w,
                           const float* __restrict__ cls_b,
                           const float* __restrict__ skip)
{
    int b = blockIdx.x;
    int m = threadIdx.x;
    __shared__ float xr[512];
    for (int k = m; k < 512; k += 256)
        xr[k] = x[(size_t)(b * 1025) * 512 + k];
    __syncthreads();
    float acc = cls_b[m];
    for (int k = 0; k < 512; k++)
        acc = fmaf(xr[k], cls_w[(size_t)m * 512 + k], acc);
    size_t pos = (size_t)b * L_SEQ * 256 + m;
    g_xx[pos] = acc + skip[pos];
}

// ---------------- causal depthwise conv4 + SiLU ----------------------------
__global__ void conv_silu_kernel(const float* __restrict__ cw,
                                 const float* __restrict__ cb)
{
    int idx = blockIdx.x * blockDim.x + threadIdx.x;
    if (idx >= BLTOT * DINNER) return;
    int d  = idx & 511;
    int bl = idx >> 9;
    int l  = bl % L_SEQ;
    float acc = cb[d];
#pragma unroll
    for (int k = 0; k < 4; k++) {
        int lp = l - 3 + k;
        if (lp >= 0)
            acc = fmaf(cw[d * 4 + k], g_xz[(size_t)(bl - 3 + k) * 1024 + d], acc);
    }
    g_xi[(size_t)bl * 512 + d] = acc / (1.f + __expf(-acc));
}

// ---------------- delta = softplus(dt @ Wdt^T + bdt) -----------------------
__global__ void __launch_bounds__(512)
delta_kernel(const float* __restrict__ dt_w, const float* __restrict__ dt_b)
{
    __shared__ float sW[16 * 512];    // transposed [r][d]
    int tid = threadIdx.x;
    for (int i = tid; i < 8192; i += 512) {
        int dd = i >> 4, r = i & 15;
        sW[r * 512 + dd] = dt_w[i];
    }
    __syncthreads();
    float bias = dt_b[tid];
    for (int row = blockIdx.x; row < BLTOT; row += gridDim.x) {
        const float* dr = g_dbc + (size_t)row * 48;
        float acc = bias;
#pragma unroll
        for (int r = 0; r < 16; r++)
            acc = fmaf(dr[r], sW[r * 512 + tid], acc);
        float sp = (acc > 20.f) ? acc : log1pf(__expf(acc));
        g_delta[(size_t)row * 512 + tid] = sp;
    }
}

// ---------------- scan helpers ---------------------------------------------
__device__ __forceinline__ void load_A(const float* __restrict__ A_log, int d,
                                       float* Aarr, float& A0, bool& fast)
{
#pragma unroll
    for (int n = 0; n < 16; n++) Aarr[n] = -expf(A_log[d * 16 + n]);
    A0 = Aarr[0];
    fast = true;
#pragma unroll
    for (int n = 1; n < 16; n++) {
        float expect = (float)(n + 1) * A0;
        if (fabsf(Aarr[n] - expect) > 1e-3f * fabsf(expect) + 1e-6f) fast = false;
    }
}

__device__ __forceinline__ void load_BC(size_t bl, int off, float* out)
{
    const float4* p = reinterpret_cast<const float4*>(g_dbc + bl * 48 + off);
    float4 v0 = p[0], v1 = p[1], v2 = p[2], v3 = p[3];
    out[0]=v0.x; out[1]=v0.y; out[2]=v0.z; out[3]=v0.w;
    out[4]=v1.x; out[5]=v1.y; out[6]=v1.z; out[7]=v1.w;
    out[8]=v2.x; out[9]=v2.y; out[10]=v2.z; out[11]=v2.w;
    out[12]=v3.x; out[13]=v3.y; out[14]=v3.z; out[15]=v3.w;
}

// ---------------- scan pass 1: per-chunk (P, q) ----------------------------
__global__ void __launch_bounds__(512)
scan_p1(const float* __restrict__ A_log)
{
    int b = blockIdx.x / NCH;
    int c = blockIdx.x % NCH;
    int d = threadIdx.x;
    float Aarr[16], A0; bool fast;
    load_A(A_log, d, Aarr, A0, fast);

    float h[16], P[16];
#pragma unroll
    for (int n = 0; n < 16; n++) { h[n] = 0.f; P[n] = 1.f; }

    int t0 = c * CSZ;
    int t1 = min(t0 + CSZ, L_SEQ);
    for (int t = t0; t < t1; t++) {
        size_t bl = (size_t)b * L_SEQ + t;
        float dlt = g_delta[bl * 512 + d];
        float xv  = g_xi[bl * 512 + d];
        float Bv[16]; load_BC(bl, 16, Bv);
        float dx = dlt * xv;
        if (fast) {
            float e1 = __expf(dlt * A0);
            float a = e1;
#pragma unroll
            for (int n = 0; n < 16; n++) {
                h[n] = fmaf(h[n], a, dx * Bv[n]);
                P[n] *= a;
                a *= e1;
            }
        } else {
#pragma unroll
            for (int n = 0; n < 16; n++) {
                float a = __expf(dlt * Aarr[n]);
                h[n] = fmaf(h[n], a, dx * Bv[n]);
                P[n] *= a;
            }
        }
    }
    size_t base = ((size_t)blockIdx.x * 512 + d) * 16;
#pragma unroll
    for (int n = 0; n < 16; n++) { g_P[base + n] = P[n]; g_Q[base + n] = h[n]; }
}

// ---------------- scan chunk prefix ----------------------------------------
__global__ void scan_prefix_kernel()
{
    int tid = blockIdx.x * blockDim.x + threadIdx.x;   // 16384 threads
    int b = tid >> 13;
    int e = tid & 8191;
    float hs = 0.f;
    for (int c = 0; c < NCH; c++) {
        size_t idx = ((size_t)(b * NCH + c)) * 8192 + e;
        g_H[idx] = hs;
        hs = fmaf(g_P[idx], hs, g_Q[idx]);
    }
}

// ---------------- scan pass 2: y + gating ----------------------------------
__global__ void __launch_bounds__(512)
scan_p2(const float* __restrict__ A_log, const float* __restrict__ Dp)
{
    int b = blockIdx.x / NCH;
    int c = blockIdx.x % NCH;
    int d = threadIdx.x;
    float Aarr[16], A0; bool fast;
    load_A(A_log, d, Aarr, A0, fast);

    float h[16];
    size_t hb = (size_t)blockIdx.x * 8192 + d * 16;
#pragma unroll
    for (int n = 0; n < 16; n++) h[n] = g_H[hb + n];
    float Dd = Dp[d];

    int t0 = c * CSZ;
    int t1 = min(t0 + CSZ, L_SEQ);
    for (int t = t0; t < t1; t++) {
        size_t bl = (size_t)b * L_SEQ + t;
        float dlt = g_delta[bl * 512 + d];
        float xv  = g_xi[bl * 512 + d];
        float Bv[16]; load_BC(bl, 16, Bv);
        float Cv[16]; load_BC(bl, 32, Cv);
        float dx = dlt * xv;
        float y = 0.f;
        if (fast) {
            float e1 = __expf(dlt * A0);
            float a = e1;
#pragma unroll
            for (int n = 0; n < 16; n++) {
                h[n] = fmaf(h[n], a, dx * Bv[n]);
                y = fmaf(h[n], Cv[n], y);
                a *= e1;
            }
        } else {
#pragma unroll
            for (int n = 0; n < 16; n++) {
                float a = __expf(dlt * Aarr[n]);
                h[n] = fmaf(h[n], a, dx * Bv[n]);
                y = fmaf(h[n], Cv[n], y);
            }
        }
        float zv = g_xz[bl * 1024 + 512 + d];
        float gate = zv / (1.f + __expf(-zv));
        g_y[bl * 512 + d] = (y + xv * Dd) * gate;
    }
}

// ---------------- batch-norm (deterministic two-stage) ---------------------
__global__ void bn_partial_kernel()
{
    int m = threadIdx.x;
    float s = 0.f, s2 = 0.f;
    for (int row = blockIdx.x; row < BLTOT; row += gridDim.x) {
        float v = g_xx[(size_t)row * 256 + m];
        s += v; s2 += v * v;
    }
    g_part [blockIdx.x * 256 + m] = s;
    g_part2[blockIdx.x * 256 + m] = s2;
}

__global__ void bn_final_kernel()
{
    int m = threadIdx.x;
    float S = 0.f, S2 = 0.f;
    for (int c = 0; c < 64; c++) { S += g_part[c * 256 + m]; S2 += g_part2[c * 256 + m]; }
    float mean = S / (float)BLTOT;
    float var  = S2 / (float)BLTOT - mean * mean;
    g_mean[m] = mean;
    g_inv[m]  = rsqrtf(var + 1e-5f);
}

__global__ void bn_norm_kernel(const float* __restrict__ bn_g,
                               const float* __restrict__ bn_b,
                               float* __restrict__ out, int out_size)
{
    int idx = blockIdx.x * blockDim.x + threadIdx.x;
    if (idx < BLTOT * 256) {
        int m = idx & 255;
        out[idx] = (g_xx[idx] - g_mean[m]) * g_inv[m] * bn_g[m] + bn_b[m];
    } else if (idx < out_size) {
        out[idx] = 1024.0f;   // second tuple element: 4*N
    }
}

// ---------------- driver ----------------------------------------------------
extern "C" void kernel_launch(void* const* d_in, const int* in_sizes, int n_in,
                              void* d_out, int out_size)
{
    const float* x         = (const float*)d_in[0];
    const float* skip      = (const float*)d_in[1];
    const float* exp_w     = (const float*)d_in[2];
    const float* ln_g      = (const float*)d_in[3];
    const float* ln_b      = (const float*)d_in[4];
    const float* cls_w     = (const float*)d_in[5];
    const float* cls_b     = (const float*)d_in[6];
    const float* in_proj_w = (const float*)d_in[7];
    const float* conv_w    = (const float*)d_in[8];
    const float* conv_b    = (const float*)d_in[9];
    const float* xproj_w   = (const float*)d_in[10];
    const float* dt_w      = (const float*)d_in[11];
    const float* dt_b      = (const float*)d_in[12];
    const float* A_log     = (const float*)d_in[13];
    const float* Dp        = (const float*)d_in[14];
    const float* out_w     = (const float*)d_in[15];
    const float* bn_g      = (const float*)d_in[16];
    const float* bn_b      = (const float*)d_in[17];

    float* g_e_p;     cudaGetSymbolAddress((void**)&g_e_p,     g_e);
    float* g_xx_p;    cudaGetSymbolAddress((void**)&g_xx_p,    g_xx);
    float* g_xz_p;    cudaGetSymbolAddress((void**)&g_xz_p,    g_xz);
    float* g_xi_p;    cudaGetSymbolAddress((void**)&g_xi_p,    g_xi);
    float* g_dbc_p;   cudaGetSymbolAddress((void**)&g_dbc_p,   g_dbc);
    float* g_delta_p; cudaGetSymbolAddress((void**)&g_delta_p, g_delta);
    float* g_y_p;     cudaGetSymbolAddress((void**)&g_y_p,     g_y);

    // Stage 1: expand GEMM per batch (rows skip the cls token)
    for (int b = 0; b < 2; b++) {
        gemm_nt_kernel<<<dim3(8, 8), 256>>>(
            x + (size_t)(b * 1025 + 1) * 512, exp_w,
            g_e_p + (size_t)b * 1024 * 1024, 1024, 1024, 512);
    }
    shuffle_ln_kernel<<<8192, 256>>>(skip, ln_g, ln_b);
    cls_kernel<<<2, 256>>>(x, cls_w, cls_b, skip);

    // Stage 2: two mamba layers
    for (int i = 0; i < 2; i++) {
        gemm_nt_kernel<<<dim3(8, 65), 256>>>(
            g_xx_p, in_proj_w + (size_t)i * 1024 * 256, g_xz_p, BLTOT, 1024, 256);
        conv_silu_kernel<<<(BLTOT * DINNER + 255) / 256, 256>>>(
            conv_w + (size_t)i * 512 * 4, conv_b + (size_t)i * 512);
        gemm_nt_kernel<<<dim3(1, 65), 256>>>(
            g_xi_p, xproj_w + (size_t)i * 48 * 512, g_dbc_p, BLTOT, 48, 512);
        delta_kernel<<<256, 512>>>(dt_w + (size_t)i * 512 * 16,
                                   dt_b + (size_t)i * 512);
        scan_p1<<<2 * NCH, 512>>>(A_log + (size_t)i * 512 * 16);
        scan_prefix_kernel<<<64, 256>>>();
        scan_p2<<<2 * NCH, 512>>>(A_log + (size_t)i * 512 * 16,
                                  Dp + (size_t)i * 512);
        gemm_nt_kernel<<<dim3(2, 65), 256>>>(
            g_y_p, out_w + (size_t)i * 256 * 512, g_xx_p, BLTOT, 256, 512);
    }

    // Stage 3: batch-norm + output
    bn_partial_kernel<<<64, 256>>>();
    bn_final_kernel<<<1, 256>>>();
    int tot = out_size;
    bn_norm_kernel<<<(tot + 255) / 256, 256>>>(bn_g, bn_b, (float*)d_out, tot);
}

// round 2
// speedup vs baseline: 1.5604x; 1.5604x over previous
#include <cuda_runtime.h>
#include <math.h>

#define L_SEQ   4097
#define BLTOT   8194            // B * L_SEQ
#define DMODEL  256
#define DINNER  512
#define NCH     64              // scan chunks
#define CSZ     65              // chunk size (64*65 = 4160 >= 4097)

// ---------------- scratch (static device globals; no runtime alloc) --------
__device__ float g_e   [2048 * 1024];
__device__ float g_xx  [BLTOT * DMODEL];
__device__ float g_xz  [BLTOT * 1024];
__device__ float g_xi  [BLTOT * DINNER];
__device__ float g_dbc [BLTOT * 48];
__device__ float g_delta[BLTOT * DINNER];
__device__ float g_y   [BLTOT * DINNER];
__device__ float g_P   [2 * NCH * DINNER * 16];
__device__ float g_Q   [2 * NCH * DINNER * 16];
__device__ float g_H   [2 * NCH * DINNER * 16];
__device__ float g_part [64 * 256];
__device__ float g_part2[64 * 256];
__device__ float g_mean[256];
__device__ float g_inv [256];

// ================= tf32 tensor-core GEMM:  C = A[M,K] * W[N,K]^T ==========
// BM=BN=128, BK=32, 256 threads = 8 warps (4x2), warp tile 32x64,
// mma.m16n8k8.tf32, smem row stride 36 floats (16B aligned, conflict-free).
#define TFS 36

__device__ __forceinline__ unsigned f2tf32(float f) {
    unsigned u;
    asm("cvt.rna.tf32.f32 %0, %1;" : "=r"(u) : "f"(f));
    return u;
}

__global__ void __launch_bounds__(256)
gemm_tf32_kernel(const float* __restrict__ A, const float* __restrict__ W,
                 float* __restrict__ C, int M, int N, int K)
{
    __shared__ __align__(16) float As[128 * TFS];
    __shared__ __align__(16) float Ws[128 * TFS];
    const int tid  = threadIdx.x;
    const int warp = tid >> 5, lane = tid & 31;
    const int wm = warp >> 1, wn = warp & 1;       // 4x2 warp grid
    const int qr = lane >> 2, qc = lane & 3;
    const int m0 = blockIdx.y * 128;
    const int n0 = blockIdx.x * 128;

    float c[2][8][4];
#pragma unroll
    for (int i = 0; i < 2; i++)
#pragma unroll
        for (int j = 0; j < 8; j++)
#pragma unroll
            for (int t = 0; t < 4; t++) c[i][j][t] = 0.f;

    for (int k0 = 0; k0 < K; k0 += 32) {
        // fill As[128][32], Ws[128][32] (tf32-converted), stride TFS
#pragma unroll
        for (int i = 0; i < 4; i++) {
            int s  = tid + i * 256;          // 0..1023
            int r  = s >> 3;
            int kk4 = (s & 7) << 2;
            float4 va = make_float4(0.f, 0.f, 0.f, 0.f);
            if (m0 + r < M)
                va = *reinterpret_cast<const float4*>(A + (size_t)(m0 + r) * K + k0 + kk4);
            unsigned* pa = reinterpret_cast<unsigned*>(&As[r * TFS + kk4]);
            *reinterpret_cast<uint4*>(pa) =
                make_uint4(f2tf32(va.x), f2tf32(va.y), f2tf32(va.z), f2tf32(va.w));
            float4 vw = make_float4(0.f, 0.f, 0.f, 0.f);
            if (n0 + r < N)
                vw = *reinterpret_cast<const float4*>(W + (size_t)(n0 + r) * K + k0 + kk4);
            unsigned* pw = reinterpret_cast<unsigned*>(&Ws[r * TFS + kk4]);
            *reinterpret_cast<uint4*>(pw) =
                make_uint4(f2tf32(vw.x), f2tf32(vw.y), f2tf32(vw.z), f2tf32(vw.w));
        }
        __syncthreads();

        const unsigned* Au = reinterpret_cast<const unsigned*>(As);
        const unsigned* Wu = reinterpret_cast<const unsigned*>(Ws);
#pragma unroll
        for (int kk = 0; kk < 32; kk += 8) {
            unsigned a[2][4];
#pragma unroll
            for (int mt = 0; mt < 2; mt++) {
                int row = wm * 32 + mt * 16 + qr;
                a[mt][0] = Au[row * TFS + kk + qc];
                a[mt][1] = Au[(row + 8) * TFS + kk + qc];
                a[mt][2] = Au[row * TFS + kk + qc + 4];
                a[mt][3] = Au[(row + 8) * TFS + kk + qc + 4];
            }
            unsigned b[8][2];
#pragma unroll
            for (int nt = 0; nt < 8; nt++) {
                int col = wn * 64 + nt * 8 + qr;
                b[nt][0] = Wu[col * TFS + kk + qc];
                b[nt][1] = Wu[col * TFS + kk + qc + 4];
            }
#pragma unroll
            for (int mt = 0; mt < 2; mt++)
#pragma unroll
                for (int nt = 0; nt < 8; nt++) {
                    asm volatile(
                        "mma.sync.aligned.m16n8k8.row.col.f32.tf32.tf32.f32 "
                        "{%0,%1,%2,%3}, {%4,%5,%6,%7}, {%8,%9}, {%0,%1,%2,%3};\n"
                        : "+f"(c[mt][nt][0]), "+f"(c[mt][nt][1]),
                          "+f"(c[mt][nt][2]), "+f"(c[mt][nt][3])
                        : "r"(a[mt][0]), "r"(a[mt][1]), "r"(a[mt][2]), "r"(a[mt][3]),
                          "r"(b[nt][0]), "r"(b[nt][1]));
                }
        }
        __syncthreads();
    }

    // store
#pragma unroll
    for (int mt = 0; mt < 2; mt++) {
#pragma unroll
        for (int nt = 0; nt < 8; nt++) {
            int gr = m0 + wm * 32 + mt * 16 + qr;
            int gc = n0 + wn * 64 + nt * 8 + qc * 2;
            if (gr < M) {
                if (gc     < N) C[(size_t)gr * N + gc]     = c[mt][nt][0];
                if (gc + 1 < N) C[(size_t)gr * N + gc + 1] = c[mt][nt][1];
            }
            if (gr + 8 < M) {
                if (gc     < N) C[(size_t)(gr + 8) * N + gc]     = c[mt][nt][2];
                if (gc + 1 < N) C[(size_t)(gr + 8) * N + gc + 1] = c[mt][nt][3];
            }
        }
    }
}

// ---------------- generic fp32 GEMM (kept for xproj, precision-critical) ---
__global__ void __launch_bounds__(256)
gemm_nt_kernel(const float* __restrict__ A, const float* __restrict__ W,
               float* __restrict__ C, int M, int N, int K)
{
    __shared__ __align__(16) float As[16][128];
    __shared__ __align__(16) float Ws[16][128];
    const int tid = threadIdx.x;
    const int m0 = blockIdx.y * 128;
    const int n0 = blockIdx.x * 128;
    const int tr = tid >> 4;
    const int tc = tid & 15;
    const int rowBase = tr * 8;
    const int colBase = tc * 8;

    float acc[8][8];
#pragma unroll
    for (int i = 0; i < 8; i++)
#pragma unroll
        for (int j = 0; j < 8; j++) acc[i][j] = 0.f;

    for (int k0 = 0; k0 < K; k0 += 16) {
#pragma unroll
        for (int f = tid; f < 512; f += 256) {
            int r  = f >> 2;
            int c4 = (f & 3) << 2;
            int gm = m0 + r;
            float4 v = make_float4(0.f, 0.f, 0.f, 0.f);
            if (gm < M)
                v = *reinterpret_cast<const float4*>(A + (size_t)gm * K + k0 + c4);
            As[c4 + 0][r] = v.x; As[c4 + 1][r] = v.y;
            As[c4 + 2][r] = v.z; As[c4 + 3][r] = v.w;
        }
#pragma unroll
        for (int f = tid; f < 512; f += 256) {
            int r  = f >> 2;
            int c4 = (f & 3) << 2;
            int gn = n0 + r;
            float4 v = make_float4(0.f, 0.f, 0.f, 0.f);
            if (gn < N)
                v = *reinterpret_cast<const float4*>(W + (size_t)gn * K + k0 + c4);
            Ws[c4 + 0][r] = v.x; Ws[c4 + 1][r] = v.y;
            Ws[c4 + 2][r] = v.z; Ws[c4 + 3][r] = v.w;
        }
        __syncthreads();
#pragma unroll
        for (int kk = 0; kk < 16; kk++) {
            const float4* Ar = reinterpret_cast<const float4*>(&As[kk][rowBase]);
            const float4* Br = reinterpret_cast<const float4*>(&Ws[kk][colBase]);
            float4 a0 = Ar[0], a1 = Ar[1];
            float4 b0 = Br[0], b1 = Br[1];
            float a[8] = {a0.x, a0.y, a0.z, a0.w, a1.x, a1.y, a1.z, a1.w};
            float b[8] = {b0.x, b0.y, b0.z, b0.w, b1.x, b1.y, b1.z, b1.w};
#pragma unroll
            for (int i = 0; i < 8; i++)
#pragma unroll
                for (int j = 0; j < 8; j++)
                    acc[i][j] = fmaf(a[i], b[j], acc[i][j]);
        }
        __syncthreads();
    }
#pragma unroll
    for (int i = 0; i < 8; i++) {
        int gm = m0 + rowBase + i;
        if (gm >= M) continue;
#pragma unroll
        for (int j = 0; j < 8; j++) {
            int gn = n0 + colBase + j;
            if (gn < N) C[(size_t)gm * N + gn] = acc[i][j];
        }
    }
}

// ---------------- pixel-shuffle + LayerNorm + skip -------------------------
__global__ void shuffle_ln_kernel(const float* __restrict__ skip,
                                  const float* __restrict__ ln_g,
                                  const float* __restrict__ ln_b)
{
    int blk = blockIdx.x;
    int row = blk >> 2;          // b*1024 + t*256 + n
    int cpq = blk & 3;
    int tid = threadIdx.x;
    int b = row >> 10;
    int t = (row >> 8) & 3;
    int n = row & 255;

    float v = g_e[(size_t)row * 1024 + cpq * 256 + tid];

    float s = v, s2 = v * v;
#pragma unroll
    for (int o = 16; o; o >>= 1) {
        s  += __shfl_xor_sync(0xffffffffu, s,  o);
        s2 += __shfl_xor_sync(0xffffffffu, s2, o);
    }
    __shared__ float ss[8], ss2[8];
    __shared__ float smean, svar;
    int lane = tid & 31, wid = tid >> 5;
    if (lane == 0) { ss[wid] = s; ss2[wid] = s2; }
    __syncthreads();
    if (tid == 0) {
        float S = 0.f, S2 = 0.f;
#pragma unroll
        for (int i = 0; i < 8; i++) { S += ss[i]; S2 += ss2[i]; }
        float mu = S * (1.f / 256.f);
        smean = mu;
        svar  = S2 * (1.f / 256.f) - mu * mu;
    }
    __syncthreads();
    float y = (v - smean) * rsqrtf(svar + 1e-5f) * ln_g[tid] + ln_b[tid];

    int h = n >> 4, w = n & 15, p = cpq >> 1, q = cpq & 1;
    int j = h * 64 + p * 32 + w * 2 + q;
    size_t pos = ((size_t)b * L_SEQ + 1 + t * 1024 + j) * 256 + tid;
    g_xx[pos] = y + skip[pos];
}

// ---------------- cls token projection + skip (warp per output) ------------
__global__ void __launch_bounds__(256)
cls_kernel(const float* __restrict__ x,
           const float* __restrict__ cls_w,
           const float* __restrict__ cls_b,
           const float* __restrict__ skip)
{
    int gw   = blockIdx.x * 8 + (threadIdx.x >> 5);   // 0..511
    int lane = threadIdx.x & 31;
    int b = gw >> 8;
    int m = gw & 255;
    const float* xr = x + (size_t)(b * 1025) * 512;
    const float* wr = cls_w + (size_t)m * 512;
    float acc = 0.f;
#pragma unroll
    for (int k = lane * 4; k < 512; k += 128) {
        float4 xv = *reinterpret_cast<const float4*>(xr + k);
        float4 wv = *reinterpret_cast<const float4*>(wr + k);
        acc = fmaf(xv.x, wv.x, acc);
        acc = fmaf(xv.y, wv.y, acc);
        acc = fmaf(xv.z, wv.z, acc);
        acc = fmaf(xv.w, wv.w, acc);
    }
#pragma unroll
    for (int o = 16; o; o >>= 1) acc += __shfl_xor_sync(0xffffffffu, acc, o);
    if (lane == 0) {
        size_t pos = (size_t)b * L_SEQ * 256 + m;
        g_xx[pos] = acc + cls_b[m] + skip[pos];
    }
}

// ---------------- causal depthwise conv4 + SiLU ----------------------------
__global__ void conv_silu_kernel(const float* __restrict__ cw,
                                 const float* __restrict__ cb)
{
    int idx = blockIdx.x * blockDim.x + threadIdx.x;
    if (idx >= BLTOT * DINNER) return;
    int d  = idx & 511;
    int bl = idx >> 9;
    int l  = bl % L_SEQ;
    float acc = cb[d];
#pragma unroll
    for (int k = 0; k < 4; k++) {
        int lp = l - 3 + k;
        if (lp >= 0)
            acc = fmaf(cw[d * 4 + k], g_xz[(size_t)(bl - 3 + k) * 1024 + d], acc);
    }
    g_xi[(size_t)bl * 512 + d] = acc / (1.f + __expf(-acc));
}

// ---------------- delta = softplus(dt @ Wdt^T + bdt) -----------------------
__global__ void __launch_bounds__(512)
delta_kernel(const float* __restrict__ dt_w, const float* __restrict__ dt_b)
{
    __shared__ float sW[16 * 512];    // transposed [r][d]
    int tid = threadIdx.x;
    for (int i = tid; i < 8192; i += 512) {
        int dd = i >> 4, r = i & 15;
        sW[r * 512 + dd] = dt_w[i];
    }
    __syncthreads();
    float bias = dt_b[tid];
    for (int row = blockIdx.x; row < BLTOT; row += gridDim.x) {
        const float* dr = g_dbc + (size_t)row * 48;
        float acc = bias;
#pragma unroll
        for (int r = 0; r < 16; r++)
            acc = fmaf(dr[r], sW[r * 512 + tid], acc);
        float sp = (acc > 20.f) ? acc : log1pf(__expf(acc));
        g_delta[(size_t)row * 512 + tid] = sp;
    }
}

// ---------------- scan helpers ---------------------------------------------
__device__ __forceinline__ void load_A(const float* __restrict__ A_log, int d,
                                       float* Aarr, float& A0, bool& fast)
{
#pragma unroll
    for (int n = 0; n < 16; n++) Aarr[n] = -expf(A_log[d * 16 + n]);
    A0 = Aarr[0];
    fast = true;
#pragma unroll
    for (int n = 1; n < 16; n++) {
        float expect = (float)(n + 1) * A0;
        if (fabsf(Aarr[n] - expect) > 1e-3f * fabsf(expect) + 1e-6f) fast = false;
    }
}

__device__ __forceinline__ void load_BC(size_t bl, int off, float* out)
{
    const float4* p = reinterpret_cast<const float4*>(g_dbc + bl * 48 + off);
    float4 v0 = p[0], v1 = p[1], v2 = p[2], v3 = p[3];
    out[0]=v0.x; out[1]=v0.y; out[2]=v0.z; out[3]=v0.w;
    out[4]=v1.x; out[5]=v1.y; out[6]=v1.z; out[7]=v1.w;
    out[8]=v2.x; out[9]=v2.y; out[10]=v2.z; out[11]=v2.w;
    out[12]=v3.x; out[13]=v3.y; out[14]=v3.z; out[15]=v3.w;
}

// ---------------- scan pass 1: per-chunk (P, q) ----------------------------
__global__ void __launch_bounds__(512)
scan_p1(const float* __restrict__ A_log)
{
    int b = blockIdx.x / NCH;
    int c = blockIdx.x % NCH;
    int d = threadIdx.x;
    float Aarr[16], A0; bool fast;
    load_A(A_log, d, Aarr, A0, fast);

    float h[16], P[16];
#pragma unroll
    for (int n = 0; n < 16; n++) { h[n] = 0.f; P[n] = 1.f; }

    int t0 = c * CSZ;
    int t1 = min(t0 + CSZ, L_SEQ);
    for (int t = t0; t < t1; t++) {
        size_t bl = (size_t)b * L_SEQ + t;
        float dlt = g_delta[bl * 512 + d];
        float xv  = g_xi[bl * 512 + d];
        float Bv[16]; load_BC(bl, 16, Bv);
        float dx = dlt * xv;
        if (fast) {
            float e1 = __expf(dlt * A0);
            float a = e1;
#pragma unroll
            for (int n = 0; n < 16; n++) {
                h[n] = fmaf(h[n], a, dx * Bv[n]);
                P[n] *= a;
                a *= e1;
            }
        } else {
#pragma unroll
            for (int n = 0; n < 16; n++) {
                float a = __expf(dlt * Aarr[n]);
                h[n] = fmaf(h[n], a, dx * Bv[n]);
                P[n] *= a;
            }
        }
    }
    size_t base = ((size_t)blockIdx.x * 512 + d) * 16;
#pragma unroll
    for (int n = 0; n < 16; n++) { g_P[base + n] = P[n]; g_Q[base + n] = h[n]; }
}

// ---------------- scan chunk prefix ----------------------------------------
__global__ void scan_prefix_kernel()
{
    int tid = blockIdx.x * blockDim.x + threadIdx.x;   // 16384 threads
    int b = tid >> 13;
    int e = tid & 8191;
    float hs = 0.f;
    for (int c = 0; c < NCH; c++) {
        size_t idx = ((size_t)(b * NCH + c)) * 8192 + e;
        g_H[idx] = hs;
        hs = fmaf(g_P[idx], hs, g_Q[idx]);
    }
}

// ---------------- scan pass 2: y + gating ----------------------------------
__global__ void __launch_bounds__(512)
scan_p2(const float* __restrict__ A_log, const float* __restrict__ Dp)
{
    int b = blockIdx.x / NCH;
    int c = blockIdx.x % NCH;
    int d = threadIdx.x;
    float Aarr[16], A0; bool fast;
    load_A(A_log, d, Aarr, A0, fast);

    float h[16];
    size_t hb = (size_t)blockIdx.x * 8192 + d * 16;
#pragma unroll
    for (int n = 0; n < 16; n++) h[n] = g_H[hb + n];
    float Dd = Dp[d];

    int t0 = c * CSZ;
    int t1 = min(t0 + CSZ, L_SEQ);
    for (int t = t0; t < t1; t++) {
        size_t bl = (size_t)b * L_SEQ + t;
        float dlt = g_delta[bl * 512 + d];
        float xv  = g_xi[bl * 512 + d];
        float Bv[16]; load_BC(bl, 16, Bv);
        float Cv[16]; load_BC(bl, 32, Cv);
        float dx = dlt * xv;
        float y = 0.f;
        if (fast) {
            float e1 = __expf(dlt * A0);
            float a = e1;
#pragma unroll
            for (int n = 0; n < 16; n++) {
                h[n] = fmaf(h[n], a, dx * Bv[n]);
                y = fmaf(h[n], Cv[n], y);
                a *= e1;
            }
        } else {
#pragma unroll
            for (int n = 0; n < 16; n++) {
                float a = __expf(dlt * Aarr[n]);
                h[n] = fmaf(h[n], a, dx * Bv[n]);
                y = fmaf(h[n], Cv[n], y);
            }
        }
        float zv = g_xz[bl * 1024 + 512 + d];
        float gate = zv / (1.f + __expf(-zv));
        g_y[bl * 512 + d] = (y + xv * Dd) * gate;
    }
}

// ---------------- batch-norm (deterministic two-stage) ---------------------
__global__ void bn_partial_kernel()
{
    int m = threadIdx.x;
    float s = 0.f, s2 = 0.f;
    for (int row = blockIdx.x; row < BLTOT; row += gridDim.x) {
        float v = g_xx[(size_t)row * 256 + m];
        s += v; s2 += v * v;
    }
    g_part [blockIdx.x * 256 + m] = s;
    g_part2[blockIdx.x * 256 + m] = s2;
}

__global__ void bn_final_kernel()
{
    int m = threadIdx.x;
    float S = 0.f, S2 = 0.f;
    for (int c = 0; c < 64; c++) { S += g_part[c * 256 + m]; S2 += g_part2[c * 256 + m]; }
    float mean = S / (float)BLTOT;
    float var  = S2 / (float)BLTOT - mean * mean;
    g_mean[m] = mean;
    g_inv[m]  = rsqrtf(var + 1e-5f);
}

__global__ void bn_norm_kernel(const float* __restrict__ bn_g,
                               const float* __restrict__ bn_b,
                               float* __restrict__ out, int out_size)
{
    int idx = blockIdx.x * blockDim.x + threadIdx.x;
    if (idx < BLTOT * 256) {
        int m = idx & 255;
        out[idx] = (g_xx[idx] - g_mean[m]) * g_inv[m] * bn_g[m] + bn_b[m];
    } else if (idx < out_size) {
        out[idx] = 1024.0f;   // second tuple element: 4*N
    }
}

// ---------------- driver ----------------------------------------------------
extern "C" void kernel_launch(void* const* d_in, const int* in_sizes, int n_in,
                              void* d_out, int out_size)
{
    const float* x         = (const float*)d_in[0];
    const float* skip      = (const float*)d_in[1];
    const float* exp_w     = (const float*)d_in[2];
    const float* ln_g      = (const float*)d_in[3];
    const float* ln_b      = (const float*)d_in[4];
    const float* cls_w     = (const float*)d_in[5];
    const float* cls_b     = (const float*)d_in[6];
    const float* in_proj_w = (const float*)d_in[7];
    const float* conv_w    = (const float*)d_in[8];
    const float* conv_b    = (const float*)d_in[9];
    const float* xproj_w   = (const float*)d_in[10];
    const float* dt_w      = (const float*)d_in[11];
    const float* dt_b      = (const float*)d_in[12];
    const float* A_log     = (const float*)d_in[13];
    const float* Dp        = (const float*)d_in[14];
    const float* out_w     = (const float*)d_in[15];
    const float* bn_g      = (const float*)d_in[16];
    const float* bn_b      = (const float*)d_in[17];

    float* g_e_p;     cudaGetSymbolAddress((void**)&g_e_p,     g_e);
    float* g_xx_p;    cudaGetSymbolAddress((void**)&g_xx_p,    g_xx);
    float* g_xz_p;    cudaGetSymbolAddress((void**)&g_xz_p,    g_xz);
    float* g_xi_p;    cudaGetSymbolAddress((void**)&g_xi_p,    g_xi);
    float* g_dbc_p;   cudaGetSymbolAddress((void**)&g_dbc_p,   g_dbc);
    float* g_y_p;     cudaGetSymbolAddress((void**)&g_y_p,     g_y);

    // Stage 1: expand GEMM per batch (rows skip the cls token)
    for (int b = 0; b < 2; b++) {
        gemm_tf32_kernel<<<dim3(8, 8), 256>>>(
            x + (size_t)(b * 1025 + 1) * 512, exp_w,
            g_e_p + (size_t)b * 1024 * 1024, 1024, 1024, 512);
    }
    shuffle_ln_kernel<<<8192, 256>>>(skip, ln_g, ln_b);
    cls_kernel<<<64, 256>>>(x, cls_w, cls_b, skip);

    // Stage 2: two mamba layers
    for (int i = 0; i < 2; i++) {
        gemm_tf32_kernel<<<dim3(8, 65), 256>>>(
            g_xx_p, in_proj_w + (size_t)i * 1024 * 256, g_xz_p, BLTOT, 1024, 256);
        conv_silu_kernel<<<(BLTOT * DINNER + 255) / 256, 256>>>(
            conv_w + (size_t)i * 512 * 4, conv_b + (size_t)i * 512);
        gemm_nt_kernel<<<dim3(1, 65), 256>>>(
            g_xi_p, xproj_w + (size_t)i * 48 * 512, g_dbc_p, BLTOT, 48, 512);
        delta_kernel<<<256, 512>>>(dt_w + (size_t)i * 512 * 16,
                                   dt_b + (size_t)i * 512);
        scan_p1<<<2 * NCH, 512>>>(A_log + (size_t)i * 512 * 16);
        scan_prefix_kernel<<<64, 256>>>();
        scan_p2<<<2 * NCH, 512>>>(A_log + (size_t)i * 512 * 16,
                                  Dp + (size_t)i * 512);
        gemm_tf32_kernel<<<dim3(2, 65), 256>>>(
            g_y_p, out_w + (size_t)i * 256 * 512, g_xx_p, BLTOT, 256, 512);
    }

    // Stage 3: batch-norm + output
    bn_partial_kernel<<<64, 256>>>();
    bn_final_kernel<<<1, 256>>>();
    int tot = out_size;
    bn_norm_kernel<<<(tot + 255) / 256, 256>>>(bn_g, bn_b, (float*)d_out, tot);
}